// round 2
// baseline (speedup 1.0000x reference)
#include <cuda_runtime.h>
#include <math.h>

#define NN 100000
#define NE 600000
#define HD 128
#define PADW 132
#define TILE 128

typedef unsigned long long u64;

// scatter-sum scratch (allowed: __device__ global, not runtime alloc)
__device__ float g_mi[(size_t)NN * HD];

constexpr int SMEM_FLOATS = TILE * PADW * 2 + HD * HD + 512;
constexpr int SMEM_BYTES  = SMEM_FLOATS * 4;   // ~203 KB

// ---------------------------------------------------------------- f32x2 ops

__device__ __forceinline__ u64 dup2(float v) {
    u64 r;
    asm("mov.b64 %0, {%1, %1};" : "=l"(r) : "f"(v));
    return r;
}
__device__ __forceinline__ void unpack2(u64 p, float& lo, float& hi) {
    asm("mov.b64 {%0, %1}, %2;" : "=f"(lo), "=f"(hi) : "l"(p));
}
__device__ __forceinline__ void fma2(u64& d, u64 a, u64 b) {
    asm("fma.rn.f32x2 %0, %1, %2, %0;" : "+l"(d) : "l"(a), "l"(b));
}
__device__ __forceinline__ void add2(u64& d, u64 a) {
    asm("add.rn.f32x2 %0, %0, %1;" : "+l"(d) : "l"(a));
}

// ---------------------------------------------------------------- helpers

__device__ __forceinline__ void load_w128(float* __restrict__ sW,
                                          const float* __restrict__ g, int tid) {
    const float4* src = (const float4*)g;
    float4* dst = (float4*)sW;
#pragma unroll
    for (int i = 0; i < 16; ++i) dst[tid + i * 256] = src[tid + i * 256];
}

// acc[i][j] holds packed pair (col tx8+2j, tx8+2j+1) for row ty+16i
__device__ __forceinline__ void init_bias(u64 acc[8][4],
                                          const float* __restrict__ b, int tx8) {
    ulonglong2 b0 = *(const ulonglong2*)(b + tx8);       // 32B-aligned
    ulonglong2 b1 = *(const ulonglong2*)(b + tx8 + 4);
#pragma unroll
    for (int i = 0; i < 8; ++i) {
        acc[i][0] = b0.x; acc[i][1] = b0.y;
        acc[i][2] = b1.x; acc[i][3] = b1.y;
    }
}

// C[128x128] += A[128xPADW] * W[128x128] using packed f32x2 FMA
__device__ __forceinline__ void gemm128(const float* __restrict__ sA,
                                        const float* __restrict__ sW,
                                        u64 acc[8][4], int ty, int tx8) {
    const float* a0 = sA + ty * PADW;
#pragma unroll 4
    for (int k = 0; k < HD; ++k) {
        const ulonglong2* w = (const ulonglong2*)(sW + k * HD + tx8);
        ulonglong2 b0 = w[0];   // packed cols (0,1),(2,3)
        ulonglong2 b1 = w[1];   // packed cols (4,5),(6,7)
        u64 a[8];
#pragma unroll
        for (int i = 0; i < 8; ++i) a[i] = dup2(a0[(i << 4) * PADW + k]);
#pragma unroll
        for (int i = 0; i < 8; ++i) {
            fma2(acc[i][0], a[i], b0.x);
            fma2(acc[i][1], a[i], b0.y);
            fma2(acc[i][2], a[i], b1.x);
            fma2(acc[i][3], a[i], b1.y);
        }
    }
}

// MODE: 0 = tanh, 1 = leaky-relu(0.01), 2 = identity
template <int MODE>
__device__ __forceinline__ void store_acc(float* __restrict__ buf,
                                          u64 acc[8][4], int ty, int tx8) {
#pragma unroll
    for (int i = 0; i < 8; ++i) {
        float v[8];
#pragma unroll
        for (int j = 0; j < 4; ++j) unpack2(acc[i][j], v[2 * j], v[2 * j + 1]);
#pragma unroll
        for (int j = 0; j < 8; ++j) {
            float t = v[j];
            if (MODE == 0)      t = tanhf(t);
            else if (MODE == 1) t = (t > 0.f) ? t : 0.01f * t;
            v[j] = t;
        }
        float* p = buf + (ty + (i << 4)) * PADW + tx8;
        *(float4*)p       = make_float4(v[0], v[1], v[2], v[3]);
        *(float4*)(p + 4) = make_float4(v[4], v[5], v[6], v[7]);
    }
}

// ---------------------------------------------------------------- kernels

__global__ void zero_mi_kernel() {
    int i = blockIdx.x * blockDim.x + threadIdx.x;
    ((float4*)g_mi)[i] = make_float4(0.f, 0.f, 0.f, 0.f);  // NN*HD/4 float4s
}

__global__ void __launch_bounds__(256, 1)
edge_kernel(const float* __restrict__ x, const float* __restrict__ pos,
            const int* __restrict__ ei,
            const float* __restrict__ few1, const float* __restrict__ feb1,
            const float* __restrict__ few2, const float* __restrict__ feb2,
            const float* __restrict__ finfw, const float* __restrict__ finfb) {
    extern __shared__ float sm[];
    float* sA = sm;
    float* sB = sm + TILE * PADW;
    float* sW = sB + TILE * PADW;
    float* sDist = sW + HD * HD;
    float* sE    = sDist + TILE;
    int*   sSrc  = (int*)(sE + TILE);
    int*   sEnd  = sSrc + TILE;

    const int tid  = threadIdx.x;
    const int base = blockIdx.x * TILE;
    int nrows = NE - base; if (nrows > TILE) nrows = TILE;

    if (tid < TILE) {
        int s = 0, e = 0; float dist = 0.f;
        if (tid < nrows) {
            s = ei[base + tid];
            e = ei[NE + base + tid];
            float dx = pos[3 * s + 0] - pos[3 * e + 0];
            float dy = pos[3 * s + 1] - pos[3 * e + 1];
            float dz = pos[3 * s + 2] - pos[3 * e + 2];
            dx *= dx; dy *= dy; dz *= dz;               // elementwise square
            dist = sqrtf(dx * dx + dy * dy + dz * dz);  // ||d^2||_2
        }
        sSrc[tid] = s; sEnd[tid] = e; sDist[tid] = dist;
    }
    __syncthreads();

    // gather x[src] -> sA, x[end] -> sB
    for (int idx = tid; idx < TILE * 32; idx += 256) {
        int r = idx >> 5, c = (idx & 31) << 2;
        *(float4*)(sA + r * PADW + c) = *(const float4*)(x + (size_t)sSrc[r] * HD + c);
        *(float4*)(sB + r * PADW + c) = *(const float4*)(x + (size_t)sEnd[r] * HD + c);
    }
    load_w128(sW, few1, tid);                 // fe_w1 rows 0..127 (src part)
    __syncthreads();

    const int ty = tid >> 4, tx8 = (tid & 15) << 3;
    u64 acc[8][4];
    {   // acc = b1 + dist * fe_w1[256,:]
        ulonglong2 b0 = *(const ulonglong2*)(feb1 + tx8);
        ulonglong2 b1 = *(const ulonglong2*)(feb1 + tx8 + 4);
        ulonglong2 w0 = *(const ulonglong2*)(few1 + 256 * HD + tx8);
        ulonglong2 w1 = *(const ulonglong2*)(few1 + 256 * HD + tx8 + 4);
#pragma unroll
        for (int i = 0; i < 8; ++i) {
            u64 d = dup2(sDist[ty + (i << 4)]);
            acc[i][0] = b0.x; fma2(acc[i][0], d, w0.x);
            acc[i][1] = b0.y; fma2(acc[i][1], d, w0.y);
            acc[i][2] = b1.x; fma2(acc[i][2], d, w1.x);
            acc[i][3] = b1.y; fma2(acc[i][3], d, w1.y);
        }
    }
    gemm128(sA, sW, acc, ty, tx8);
    __syncthreads();
    load_w128(sW, few1 + 128 * HD, tid);      // fe_w1 rows 128..255 (end part)
    __syncthreads();
    gemm128(sB, sW, acc, ty, tx8);
    __syncthreads();
    store_acc<0>(sA, acc, ty, tx8);           // H1 = tanh(...) -> sA
    __syncthreads();
    load_w128(sW, few2, tid);
    __syncthreads();
    init_bias(acc, feb2, tx8);
    gemm128(sA, sW, acc, ty, tx8);
    store_acc<0>(sB, acc, ty, tx8);           // H2 = m_ij -> sB
    __syncthreads();

    // e_ij = tanh(H2 . finf_w + b): warp per 16 edges
    {
        int warp = tid >> 5, lane = tid & 31;
        float fw0 = finfw[lane], fw1 = finfw[lane + 32];
        float fw2 = finfw[lane + 64], fw3 = finfw[lane + 96];
        float fb = finfb[0];
        for (int it = 0; it < 16; ++it) {
            int r = warp * 16 + it;
            const float* row = sB + r * PADW;
            float v = row[lane] * fw0 + row[lane + 32] * fw1
                    + row[lane + 64] * fw2 + row[lane + 96] * fw3;
#pragma unroll
            for (int off = 16; off; off >>= 1) v += __shfl_xor_sync(0xffffffffu, v, off);
            if (lane == 0) sE[r] = tanhf(v + fb);
        }
    }
    __syncthreads();

    // scatter-add e*m to source node
    for (int idx = tid; idx < nrows * HD; idx += 256) {
        int r = idx >> 7, c = idx & 127;
        atomicAdd(&g_mi[(size_t)sSrc[r] * HD + c], sE[r] * sB[r * PADW + c]);
    }
}

__global__ void __launch_bounds__(256, 1)
node_kernel(const float* __restrict__ x,
            const float* __restrict__ fhw1, const float* __restrict__ fhb1,
            const float* __restrict__ fhw2, const float* __restrict__ fhb2,
            const float* __restrict__ l1w, const float* __restrict__ l1b,
            const float* __restrict__ l2w, const float* __restrict__ l2b,
            const float* __restrict__ l3w, const float* __restrict__ l3b,
            const float* __restrict__ l4w, const float* __restrict__ l4b,
            const float* __restrict__ l5w, const float* __restrict__ l5b,
            float* __restrict__ out) {
    extern __shared__ float sm[];
    float* sA = sm;
    float* sB = sm + TILE * PADW;
    float* sW = sB + TILE * PADW;

    const int tid  = threadIdx.x;
    const int base = blockIdx.x * TILE;
    int nrows = NN - base; if (nrows > TILE) nrows = TILE;

    // load x rows -> sA, m_i rows -> sB (clamp OOB rows to row 0, unused)
    for (int idx = tid; idx < TILE * 32; idx += 256) {
        int r = idx >> 5, c = (idx & 31) << 2;
        int g = base + ((r < nrows) ? r : 0);
        *(float4*)(sA + r * PADW + c) = *(const float4*)(x + (size_t)g * HD + c);
        *(float4*)(sB + r * PADW + c) = *(const float4*)(g_mi + (size_t)g * HD + c);
    }
    load_w128(sW, fhw1, tid);
    __syncthreads();

    const int ty = tid >> 4, tx8 = (tid & 15) << 3;
    u64 acc[8][4];
    init_bias(acc, fhb1, tx8);
    gemm128(sA, sW, acc, ty, tx8);
    __syncthreads();
    load_w128(sW, fhw1 + 128 * HD, tid);
    __syncthreads();
    gemm128(sB, sW, acc, ty, tx8);
    __syncthreads();
    store_acc<0>(sB, acc, ty, tx8);           // H = tanh(...) -> sB
    __syncthreads();
    load_w128(sW, fhw2, tid);
    __syncthreads();
    init_bias(acc, fhb2, tx8);
#pragma unroll
    for (int i = 0; i < 8; ++i) {             // residual: + x  (16B-aligned pairs)
        const ulonglong2* p0 = (const ulonglong2*)(sA + (ty + (i << 4)) * PADW + tx8);
        ulonglong2 x0 = p0[0], x1 = p0[1];
        add2(acc[i][0], x0.x); add2(acc[i][1], x0.y);
        add2(acc[i][2], x1.x); add2(acc[i][3], x1.y);
    }
    gemm128(sB, sW, acc, ty, tx8);
    store_acc<2>(sA, acc, ty, tx8);           // x1 -> sA
    __syncthreads();

    // head: l1..l4 with leaky relu, ping-pong sA <-> sB
    const float* ws[4] = {l1w, l2w, l3w, l4w};
    const float* bs[4] = {l1b, l2b, l3b, l4b};
#pragma unroll
    for (int L = 0; L < 4; ++L) {
        const float* src = (L & 1) ? sB : sA;
        float*       dst = (L & 1) ? sA : sB;
        load_w128(sW, ws[L], tid);
        __syncthreads();
        init_bias(acc, bs[L], tx8);
        gemm128(src, sW, acc, ty, tx8);
        store_acc<1>(dst, acc, ty, tx8);
        __syncthreads();
    }
    // final activations now in sA (l4 wrote dst=sA)

    // l5: [128]->[3], warp per 16 rows
    {
        int warp = tid >> 5, lane = tid & 31;
        float w[4][3];
#pragma unroll
        for (int i = 0; i < 4; ++i) {
            int k = lane + 32 * i;
            w[i][0] = l5w[k * 3 + 0]; w[i][1] = l5w[k * 3 + 1]; w[i][2] = l5w[k * 3 + 2];
        }
        float b0 = l5b[0], b1 = l5b[1], b2 = l5b[2];
        for (int it = 0; it < 16; ++it) {
            int r = warp * 16 + it;
            const float* row = sA + r * PADW;
            float c0 = 0.f, c1 = 0.f, c2 = 0.f;
#pragma unroll
            for (int i = 0; i < 4; ++i) {
                float h = row[lane + 32 * i];
                c0 = fmaf(h, w[i][0], c0);
                c1 = fmaf(h, w[i][1], c1);
                c2 = fmaf(h, w[i][2], c2);
            }
#pragma unroll
            for (int off = 16; off; off >>= 1) {
                c0 += __shfl_xor_sync(0xffffffffu, c0, off);
                c1 += __shfl_xor_sync(0xffffffffu, c1, off);
                c2 += __shfl_xor_sync(0xffffffffu, c2, off);
            }
            if (lane == 0 && r < nrows) {
                float* o = out + (size_t)(base + r) * 3;
                o[0] = c0 + b0; o[1] = c1 + b1; o[2] = c2 + b2;
            }
        }
    }
}

// ---------------------------------------------------------------- launch

extern "C" void kernel_launch(void* const* d_in, const int* in_sizes, int n_in,
                              void* d_out, int out_size) {
    const float* x     = (const float*)d_in[0];
    const float* pos   = (const float*)d_in[1];
    const int*   ei    = (const int*)d_in[2];
    const float* few1  = (const float*)d_in[3];
    const float* feb1  = (const float*)d_in[4];
    const float* few2  = (const float*)d_in[5];
    const float* feb2  = (const float*)d_in[6];
    const float* finfw = (const float*)d_in[7];
    const float* finfb = (const float*)d_in[8];
    const float* fhw1  = (const float*)d_in[9];
    const float* fhb1  = (const float*)d_in[10];
    const float* fhw2  = (const float*)d_in[11];
    const float* fhb2  = (const float*)d_in[12];
    const float* l1w   = (const float*)d_in[13];
    const float* l1b   = (const float*)d_in[14];
    const float* l2w   = (const float*)d_in[15];
    const float* l2b   = (const float*)d_in[16];
    const float* l3w   = (const float*)d_in[17];
    const float* l3b   = (const float*)d_in[18];
    const float* l4w   = (const float*)d_in[19];
    const float* l4b   = (const float*)d_in[20];
    const float* l5w   = (const float*)d_in[21];
    const float* l5b   = (const float*)d_in[22];
    float* out = (float*)d_out;

    cudaFuncSetAttribute(edge_kernel, cudaFuncAttributeMaxDynamicSharedMemorySize, SMEM_BYTES);
    cudaFuncSetAttribute(node_kernel, cudaFuncAttributeMaxDynamicSharedMemorySize, SMEM_BYTES);

    zero_mi_kernel<<<(NN * HD / 4) / 256, 256>>>();
    edge_kernel<<<(NE + TILE - 1) / TILE, 256, SMEM_BYTES>>>(
        x, pos, ei, few1, feb1, few2, feb2, finfw, finfb);
    node_kernel<<<(NN + TILE - 1) / TILE, 256, SMEM_BYTES>>>(
        x, fhw1, fhb1, fhw2, fhb2,
        l1w, l1b, l2w, l2b, l3w, l3b, l4w, l4b, l5w, l5b, out);
}

// round 7
// speedup vs baseline: 1.3487x; 1.3487x over previous
#include <cuda_runtime.h>
#include <math.h>

#define NN 100000
#define NE 600000
#define HD 128
#define PADW 132
#define TILE 128

typedef unsigned long long u64;

// scratch (static __device__ globals are allowed; no runtime alloc)
__device__ float g_mi[(size_t)NN * HD];
__device__ float g_pa[(size_t)NN * HD];   // x @ fe_w1[0:128]
__device__ float g_pb[(size_t)NN * HD];   // x @ fe_w1[128:256]

constexpr int SMEM_FLOATS = TILE * PADW * 2 + HD * HD + 512;
constexpr int SMEM_BYTES  = SMEM_FLOATS * 4;   // ~203 KB

// ---------------------------------------------------------------- f32x2 ops

__device__ __forceinline__ u64 dup2(float v) {
    u64 r;
    asm("mov.b64 %0, {%1, %1};" : "=l"(r) : "f"(v));
    return r;
}
__device__ __forceinline__ void unpack2(u64 p, float& lo, float& hi) {
    asm("mov.b64 {%0, %1}, %2;" : "=f"(lo), "=f"(hi) : "l"(p));
}
__device__ __forceinline__ void fma2(u64& d, u64 a, u64 b) {
    asm("fma.rn.f32x2 %0, %1, %2, %0;" : "+l"(d) : "l"(a), "l"(b));
}
__device__ __forceinline__ void add2(u64& d, u64 a) {
    asm("add.rn.f32x2 %0, %0, %1;" : "+l"(d) : "l"(a));
}

// ---------------------------------------------------------------- helpers

__device__ __forceinline__ void load_w128(float* __restrict__ sW,
                                          const float* __restrict__ g, int tid) {
    const float4* src = (const float4*)g;
    float4* dst = (float4*)sW;
#pragma unroll
    for (int i = 0; i < 16; ++i) dst[tid + i * 256] = src[tid + i * 256];
}

__device__ __forceinline__ void init_zero(u64 acc[8][4]) {
#pragma unroll
    for (int i = 0; i < 8; ++i)
#pragma unroll
        for (int j = 0; j < 4; ++j) acc[i][j] = 0ull;
}

__device__ __forceinline__ void init_bias(u64 acc[8][4],
                                          const float* __restrict__ b, int tx8) {
    ulonglong2 b0 = *(const ulonglong2*)(b + tx8);
    ulonglong2 b1 = *(const ulonglong2*)(b + tx8 + 4);
#pragma unroll
    for (int i = 0; i < 8; ++i) {
        acc[i][0] = b0.x; acc[i][1] = b0.y;
        acc[i][2] = b1.x; acc[i][3] = b1.y;
    }
}

// C[128x128] += A[128xPADW] * W[128x128] using packed f32x2 FMA
__device__ __forceinline__ void gemm128(const float* __restrict__ sA,
                                        const float* __restrict__ sW,
                                        u64 acc[8][4], int ty, int tx8) {
    const float* a0 = sA + ty * PADW;
#pragma unroll 4
    for (int k = 0; k < HD; ++k) {
        const ulonglong2* w = (const ulonglong2*)(sW + k * HD + tx8);
        ulonglong2 b0 = w[0];
        ulonglong2 b1 = w[1];
        u64 a[8];
#pragma unroll
        for (int i = 0; i < 8; ++i) a[i] = dup2(a0[(i << 4) * PADW + k]);
#pragma unroll
        for (int i = 0; i < 8; ++i) {
            fma2(acc[i][0], a[i], b0.x);
            fma2(acc[i][1], a[i], b0.y);
            fma2(acc[i][2], a[i], b1.x);
            fma2(acc[i][3], a[i], b1.y);
        }
    }
}

// MODE: 0 = tanh, 1 = leaky-relu(0.01), 2 = identity
template <int MODE>
__device__ __forceinline__ void store_acc(float* __restrict__ buf,
                                          u64 acc[8][4], int ty, int tx8) {
#pragma unroll
    for (int i = 0; i < 8; ++i) {
        float v[8];
#pragma unroll
        for (int j = 0; j < 4; ++j) unpack2(acc[i][j], v[2 * j], v[2 * j + 1]);
#pragma unroll
        for (int j = 0; j < 8; ++j) {
            float t = v[j];
            if (MODE == 0)      t = tanhf(t);
            else if (MODE == 1) t = (t > 0.f) ? t : 0.01f * t;
            v[j] = t;
        }
        float* p = buf + (ty + (i << 4)) * PADW + tx8;
        *(float4*)p       = make_float4(v[0], v[1], v[2], v[3]);
        *(float4*)(p + 4) = make_float4(v[4], v[5], v[6], v[7]);
    }
}

// write acc rows to a global [*, HD] matrix (no activation)
__device__ __forceinline__ void store_global(float* __restrict__ g, u64 acc[8][4],
                                             int base, int nrows, int ty, int tx8) {
#pragma unroll
    for (int i = 0; i < 8; ++i) {
        int row = ty + (i << 4);
        if (row < nrows) {
            float v[8];
#pragma unroll
            for (int j = 0; j < 4; ++j) unpack2(acc[i][j], v[2 * j], v[2 * j + 1]);
            float* p = g + (size_t)(base + row) * HD + tx8;
            *(float4*)p       = make_float4(v[0], v[1], v[2], v[3]);
            *(float4*)(p + 4) = make_float4(v[4], v[5], v[6], v[7]);
        }
    }
}

// ---------------------------------------------------------------- kernels

__global__ void zero_mi_kernel() {
    int i = blockIdx.x * blockDim.x + threadIdx.x;
    ((float4*)g_mi)[i] = make_float4(0.f, 0.f, 0.f, 0.f);
}

// PA = x @ fe_w1[0:128], PB = x @ fe_w1[128:256]   (per-node precompute)
__global__ void __launch_bounds__(256, 1)
pre_kernel(const float* __restrict__ x, const float* __restrict__ few1) {
    extern __shared__ float sm[];
    float* sA = sm;
    float* sW = sm + TILE * PADW;

    const int tid  = threadIdx.x;
    const int base = blockIdx.x * TILE;
    int nrows = NN - base; if (nrows > TILE) nrows = TILE;

    for (int idx = tid; idx < TILE * 32; idx += 256) {
        int r = idx >> 5, c = (idx & 31) << 2;
        int g = base + ((r < nrows) ? r : 0);
        *(float4*)(sA + r * PADW + c) = *(const float4*)(x + (size_t)g * HD + c);
    }
    load_w128(sW, few1, tid);                 // W_top
    __syncthreads();

    const int ty = tid >> 4, tx8 = (tid & 15) << 3;
    u64 acc[8][4];
    init_zero(acc);
    gemm128(sA, sW, acc, ty, tx8);
    store_global(g_pa, acc, base, nrows, ty, tx8);
    __syncthreads();
    load_w128(sW, few1 + 128 * HD, tid);      // W_bot
    __syncthreads();
    init_zero(acc);
    gemm128(sA, sW, acc, ty, tx8);
    store_global(g_pb, acc, base, nrows, ty, tx8);
}

__global__ void __launch_bounds__(256, 1)
edge_kernel(const float* __restrict__ pos, const int* __restrict__ ei,
            const float* __restrict__ few1, const float* __restrict__ feb1,
            const float* __restrict__ few2, const float* __restrict__ feb2,
            const float* __restrict__ finfw, const float* __restrict__ finfb) {
    extern __shared__ float sm[];
    float* sA = sm;
    float* sB = sm + TILE * PADW;
    float* sW = sB + TILE * PADW;
    float* sDist = sW + HD * HD;
    float* sE    = sDist + TILE;
    int*   sSrc  = (int*)(sE + TILE);
    int*   sEnd  = sSrc + TILE;

    const int tid  = threadIdx.x;
    const int base = blockIdx.x * TILE;
    int nrows = NE - base; if (nrows > TILE) nrows = TILE;

    if (tid < TILE) {
        int s = 0, e = 0; float dist = 0.f;
        if (tid < nrows) {
            s = ei[base + tid];
            e = ei[NE + base + tid];
            float dx = pos[3 * s + 0] - pos[3 * e + 0];
            float dy = pos[3 * s + 1] - pos[3 * e + 1];
            float dz = pos[3 * s + 2] - pos[3 * e + 2];
            dx *= dx; dy *= dy; dz *= dz;               // elementwise square
            dist = sqrtf(dx * dx + dy * dy + dz * dz);  // ||d^2||_2
        }
        sSrc[tid] = s; sEnd[tid] = e; sDist[tid] = dist;
    }
    __syncthreads();

    // H1 = tanh(PA[src] + PB[end] + dist*w_row + b1)  -> sA   (fused gather)
    const float* wrow = few1 + 256 * HD;
    for (int idx = tid; idx < TILE * 32; idx += 256) {
        int r = idx >> 5, c = (idx & 31) << 2;
        float4 a = *(const float4*)(g_pa + (size_t)sSrc[r] * HD + c);
        float4 b = *(const float4*)(g_pb + (size_t)sEnd[r] * HD + c);
        float4 w = *(const float4*)(wrow + c);
        float4 bb = *(const float4*)(feb1 + c);
        float d = sDist[r];
        float4 v;
        v.x = tanhf(a.x + b.x + fmaf(d, w.x, bb.x));
        v.y = tanhf(a.y + b.y + fmaf(d, w.y, bb.y));
        v.z = tanhf(a.z + b.z + fmaf(d, w.z, bb.z));
        v.w = tanhf(a.w + b.w + fmaf(d, w.w, bb.w));
        *(float4*)(sA + r * PADW + c) = v;
    }
    load_w128(sW, few2, tid);
    __syncthreads();

    const int ty = tid >> 4, tx8 = (tid & 15) << 3;
    u64 acc[8][4];
    init_bias(acc, feb2, tx8);
    gemm128(sA, sW, acc, ty, tx8);
    store_acc<0>(sB, acc, ty, tx8);           // H2 = m_ij -> sB
    __syncthreads();

    // e_ij = tanh(H2 . finf_w + b): warp per 16 edges
    {
        int warp = tid >> 5, lane = tid & 31;
        float fw0 = finfw[lane], fw1 = finfw[lane + 32];
        float fw2 = finfw[lane + 64], fw3 = finfw[lane + 96];
        float fb = finfb[0];
        for (int it = 0; it < 16; ++it) {
            int r = warp * 16 + it;
            const float* row = sB + r * PADW;
            float v = row[lane] * fw0 + row[lane + 32] * fw1
                    + row[lane + 64] * fw2 + row[lane + 96] * fw3;
#pragma unroll
            for (int off = 16; off; off >>= 1) v += __shfl_xor_sync(0xffffffffu, v, off);
            if (lane == 0) sE[r] = tanhf(v + fb);
        }
    }
    __syncthreads();

    // scatter-add e*m to source node
    for (int idx = tid; idx < nrows * HD; idx += 256) {
        int r = idx >> 7, c = idx & 127;
        atomicAdd(&g_mi[(size_t)sSrc[r] * HD + c], sE[r] * sB[r * PADW + c]);
    }
}

__global__ void __launch_bounds__(256, 1)
node_kernel(const float* __restrict__ x,
            const float* __restrict__ fhw1, const float* __restrict__ fhb1,
            const float* __restrict__ fhw2, const float* __restrict__ fhb2,
            const float* __restrict__ l1w, const float* __restrict__ l1b,
            const float* __restrict__ l2w, const float* __restrict__ l2b,
            const float* __restrict__ l3w, const float* __restrict__ l3b,
            const float* __restrict__ l4w, const float* __restrict__ l4b,
            const float* __restrict__ l5w, const float* __restrict__ l5b,
            float* __restrict__ out) {
    extern __shared__ float sm[];
    float* sA = sm;
    float* sB = sm + TILE * PADW;
    float* sW = sB + TILE * PADW;

    const int tid  = threadIdx.x;
    const int base = blockIdx.x * TILE;
    int nrows = NN - base; if (nrows > TILE) nrows = TILE;

    for (int idx = tid; idx < TILE * 32; idx += 256) {
        int r = idx >> 5, c = (idx & 31) << 2;
        int g = base + ((r < nrows) ? r : 0);
        *(float4*)(sA + r * PADW + c) = *(const float4*)(x + (size_t)g * HD + c);
        *(float4*)(sB + r * PADW + c) = *(const float4*)(g_mi + (size_t)g * HD + c);
    }
    load_w128(sW, fhw1, tid);
    __syncthreads();

    const int ty = tid >> 4, tx8 = (tid & 15) << 3;
    u64 acc[8][4];
    init_bias(acc, fhb1, tx8);
    gemm128(sA, sW, acc, ty, tx8);
    __syncthreads();
    load_w128(sW, fhw1 + 128 * HD, tid);
    __syncthreads();
    gemm128(sB, sW, acc, ty, tx8);
    __syncthreads();
    store_acc<0>(sB, acc, ty, tx8);           // H = tanh(...) -> sB
    __syncthreads();
    load_w128(sW, fhw2, tid);
    __syncthreads();
    init_bias(acc, fhb2, tx8);
#pragma unroll
    for (int i = 0; i < 8; ++i) {             // residual: + x
        const ulonglong2* p0 = (const ulonglong2*)(sA + (ty + (i << 4)) * PADW + tx8);
        ulonglong2 x0 = p0[0], x1 = p0[1];
        add2(acc[i][0], x0.x); add2(acc[i][1], x0.y);
        add2(acc[i][2], x1.x); add2(acc[i][3], x1.y);
    }
    gemm128(sB, sW, acc, ty, tx8);
    store_acc<2>(sA, acc, ty, tx8);           // x1 -> sA
    __syncthreads();

    const float* ws[4] = {l1w, l2w, l3w, l4w};
    const float* bs[4] = {l1b, l2b, l3b, l4b};
#pragma unroll
    for (int L = 0; L < 4; ++L) {
        const float* src = (L & 1) ? sB : sA;
        float*       dst = (L & 1) ? sA : sB;
        load_w128(sW, ws[L], tid);
        __syncthreads();
        init_bias(acc, bs[L], tx8);
        gemm128(src, sW, acc, ty, tx8);
        store_acc<1>(dst, acc, ty, tx8);
        __syncthreads();
    }
    // final activations in sA

    {
        int warp = tid >> 5, lane = tid & 31;
        float w[4][3];
#pragma unroll
        for (int i = 0; i < 4; ++i) {
            int k = lane + 32 * i;
            w[i][0] = l5w[k * 3 + 0]; w[i][1] = l5w[k * 3 + 1]; w[i][2] = l5w[k * 3 + 2];
        }
        float b0 = l5b[0], b1 = l5b[1], b2 = l5b[2];
        for (int it = 0; it < 16; ++it) {
            int r = warp * 16 + it;
            const float* row = sA + r * PADW;
            float c0 = 0.f, c1 = 0.f, c2 = 0.f;
#pragma unroll
            for (int i = 0; i < 4; ++i) {
                float h = row[lane + 32 * i];
                c0 = fmaf(h, w[i][0], c0);
                c1 = fmaf(h, w[i][1], c1);
                c2 = fmaf(h, w[i][2], c2);
            }
#pragma unroll
            for (int off = 16; off; off >>= 1) {
                c0 += __shfl_xor_sync(0xffffffffu, c0, off);
                c1 += __shfl_xor_sync(0xffffffffu, c1, off);
                c2 += __shfl_xor_sync(0xffffffffu, c2, off);
            }
            if (lane == 0 && r < nrows) {
                float* o = out + (size_t)(base + r) * 3;
                o[0] = c0 + b0; o[1] = c1 + b1; o[2] = c2 + b2;
            }
        }
    }
}

// ---------------------------------------------------------------- launch

extern "C" void kernel_launch(void* const* d_in, const int* in_sizes, int n_in,
                              void* d_out, int out_size) {
    const float* x     = (const float*)d_in[0];
    const float* pos   = (const float*)d_in[1];
    const int*   ei    = (const int*)d_in[2];
    const float* few1  = (const float*)d_in[3];
    const float* feb1  = (const float*)d_in[4];
    const float* few2  = (const float*)d_in[5];
    const float* feb2  = (const float*)d_in[6];
    const float* finfw = (const float*)d_in[7];
    const float* finfb = (const float*)d_in[8];
    const float* fhw1  = (const float*)d_in[9];
    const float* fhb1  = (const float*)d_in[10];
    const float* fhw2  = (const float*)d_in[11];
    const float* fhb2  = (const float*)d_in[12];
    const float* l1w   = (const float*)d_in[13];
    const float* l1b   = (const float*)d_in[14];
    const float* l2w   = (const float*)d_in[15];
    const float* l2b   = (const float*)d_in[16];
    const float* l3w   = (const float*)d_in[17];
    const float* l3b   = (const float*)d_in[18];
    const float* l4w   = (const float*)d_in[19];
    const float* l4b   = (const float*)d_in[20];
    const float* l5w   = (const float*)d_in[21];
    const float* l5b   = (const float*)d_in[22];
    float* out = (float*)d_out;

    cudaFuncSetAttribute(pre_kernel,  cudaFuncAttributeMaxDynamicSharedMemorySize, SMEM_BYTES);
    cudaFuncSetAttribute(edge_kernel, cudaFuncAttributeMaxDynamicSharedMemorySize, SMEM_BYTES);
    cudaFuncSetAttribute(node_kernel, cudaFuncAttributeMaxDynamicSharedMemorySize, SMEM_BYTES);

    zero_mi_kernel<<<(NN * HD / 4) / 256, 256>>>();
    pre_kernel<<<(NN + TILE - 1) / TILE, 256, SMEM_BYTES>>>(x, few1);
    edge_kernel<<<(NE + TILE - 1) / TILE, 256, SMEM_BYTES>>>(
        pos, ei, few1, feb1, few2, feb2, finfw, finfb);
    node_kernel<<<(NN + TILE - 1) / TILE, 256, SMEM_BYTES>>>(
        x, fhw1, fhb1, fhw2, fhb2,
        l1w, l1b, l2w, l2b, l3w, l3b, l4w, l4b, l5w, l5b, out);
}

// round 10
// speedup vs baseline: 1.3716x; 1.0170x over previous
#include <cuda_runtime.h>
#include <math.h>

#define NN 100000
#define NE 600000
#define HD 128
#define PADW 132
#define TILE 128

typedef unsigned long long u64;

// scratch (static __device__ globals are allowed; no runtime alloc)
__device__ float g_mi[(size_t)NN * HD];
__device__ float g_pa[(size_t)NN * HD];   // x @ fe_w1[0:128]
__device__ float g_pb[(size_t)NN * HD];   // x @ fe_w1[128:256]

constexpr int SMEM_FLOATS = TILE * PADW * 2 + HD * HD + 512;
constexpr int SMEM_BYTES  = SMEM_FLOATS * 4;   // ~203 KB

// ---------------------------------------------------------------- f32x2 ops

__device__ __forceinline__ u64 dup2(float v) {
    u64 r;
    asm("mov.b64 %0, {%1, %1};" : "=l"(r) : "f"(v));
    return r;
}
__device__ __forceinline__ void unpack2(u64 p, float& lo, float& hi) {
    asm("mov.b64 {%0, %1}, %2;" : "=f"(lo), "=f"(hi) : "l"(p));
}
__device__ __forceinline__ void fma2(u64& d, u64 a, u64 b) {
    asm("fma.rn.f32x2 %0, %1, %2, %0;" : "+l"(d) : "l"(a), "l"(b));
}
__device__ __forceinline__ void add2(u64& d, u64 a) {
    asm("add.rn.f32x2 %0, %0, %1;" : "+l"(d) : "l"(a));
}

// ---------------------------------------------------------------- helpers

__device__ __forceinline__ void load_w128(float* __restrict__ sW,
                                          const float* __restrict__ g, int tid) {
    const float4* src = (const float4*)g;
    float4* dst = (float4*)sW;
#pragma unroll
    for (int i = 0; i < 16; ++i) dst[tid + i * 256] = src[tid + i * 256];
}

__device__ __forceinline__ void init_zero(u64 acc[8][4]) {
#pragma unroll
    for (int i = 0; i < 8; ++i)
#pragma unroll
        for (int j = 0; j < 4; ++j) acc[i][j] = 0ull;
}

__device__ __forceinline__ void init_bias(u64 acc[8][4],
                                          const float* __restrict__ b, int tx8) {
    ulonglong2 b0 = *(const ulonglong2*)(b + tx8);
    ulonglong2 b1 = *(const ulonglong2*)(b + tx8 + 4);
#pragma unroll
    for (int i = 0; i < 8; ++i) {
        acc[i][0] = b0.x; acc[i][1] = b0.y;
        acc[i][2] = b1.x; acc[i][3] = b1.y;
    }
}

// C[128x128] += A[128xPADW] * W[128x128], packed f32x2 FMA.
// A loaded as float4 per row per 4 k-steps (vectorized LDS: 4x fewer
// shared-memory instructions / crossbar cycles than scalar per-k loads).
__device__ __forceinline__ void gemm128(const float* __restrict__ sA,
                                        const float* __restrict__ sW,
                                        u64 acc[8][4], int ty, int tx8) {
    const float* a0 = sA + ty * PADW;
#pragma unroll 2
    for (int kk = 0; kk < HD / 4; ++kk) {
        float4 av[8];
#pragma unroll
        for (int i = 0; i < 8; ++i)
            av[i] = *(const float4*)(a0 + (i << 4) * PADW + (kk << 2));
#pragma unroll
        for (int t = 0; t < 4; ++t) {
            const int k = (kk << 2) + t;
            const ulonglong2* w = (const ulonglong2*)(sW + k * HD + tx8);
            ulonglong2 b0 = w[0];
            ulonglong2 b1 = w[1];
#pragma unroll
            for (int i = 0; i < 8; ++i) {
                float as = (t == 0) ? av[i].x : (t == 1) ? av[i].y
                         : (t == 2) ? av[i].z : av[i].w;
                u64 a = dup2(as);
                fma2(acc[i][0], a, b0.x);
                fma2(acc[i][1], a, b0.y);
                fma2(acc[i][2], a, b1.x);
                fma2(acc[i][3], a, b1.y);
            }
        }
    }
}

// MODE: 0 = tanh, 1 = leaky-relu(0.01), 2 = identity
template <int MODE>
__device__ __forceinline__ void store_acc(float* __restrict__ buf,
                                          u64 acc[8][4], int ty, int tx8) {
#pragma unroll
    for (int i = 0; i < 8; ++i) {
        float v[8];
#pragma unroll
        for (int j = 0; j < 4; ++j) unpack2(acc[i][j], v[2 * j], v[2 * j + 1]);
#pragma unroll
        for (int j = 0; j < 8; ++j) {
            float t = v[j];
            if (MODE == 0)      t = tanhf(t);
            else if (MODE == 1) t = (t > 0.f) ? t : 0.01f * t;
            v[j] = t;
        }
        float* p = buf + (ty + (i << 4)) * PADW + tx8;
        *(float4*)p       = make_float4(v[0], v[1], v[2], v[3]);
        *(float4*)(p + 4) = make_float4(v[4], v[5], v[6], v[7]);
    }
}

// write acc rows to a global [*, HD] matrix (no activation)
__device__ __forceinline__ void store_global(float* __restrict__ g, u64 acc[8][4],
                                             int base, int nrows, int ty, int tx8) {
#pragma unroll
    for (int i = 0; i < 8; ++i) {
        int row = ty + (i << 4);
        if (row < nrows) {
            float v[8];
#pragma unroll
            for (int j = 0; j < 4; ++j) unpack2(acc[i][j], v[2 * j], v[2 * j + 1]);
            float* p = g + (size_t)(base + row) * HD + tx8;
            *(float4*)p       = make_float4(v[0], v[1], v[2], v[3]);
            *(float4*)(p + 4) = make_float4(v[4], v[5], v[6], v[7]);
        }
    }
}

// ---------------------------------------------------------------- kernels

__global__ void zero_mi_kernel() {
    int i = blockIdx.x * blockDim.x + threadIdx.x;
    ((float4*)g_mi)[i] = make_float4(0.f, 0.f, 0.f, 0.f);
}

// PA = x @ fe_w1[0:128], PB = x @ fe_w1[128:256]   (per-node precompute)
__global__ void __launch_bounds__(256, 1)
pre_kernel(const float* __restrict__ x, const float* __restrict__ few1) {
    extern __shared__ float sm[];
    float* sA = sm;
    float* sW = sm + TILE * PADW;

    const int tid  = threadIdx.x;
    const int base = blockIdx.x * TILE;
    int nrows = NN - base; if (nrows > TILE) nrows = TILE;

    for (int idx = tid; idx < TILE * 32; idx += 256) {
        int r = idx >> 5, c = (idx & 31) << 2;
        int g = base + ((r < nrows) ? r : 0);
        *(float4*)(sA + r * PADW + c) = *(const float4*)(x + (size_t)g * HD + c);
    }
    load_w128(sW, few1, tid);                 // W_top
    __syncthreads();

    const int ty = tid >> 4, tx8 = (tid & 15) << 3;
    u64 acc[8][4];
    init_zero(acc);
    gemm128(sA, sW, acc, ty, tx8);
    store_global(g_pa, acc, base, nrows, ty, tx8);
    __syncthreads();
    load_w128(sW, few1 + 128 * HD, tid);      // W_bot
    __syncthreads();
    init_zero(acc);
    gemm128(sA, sW, acc, ty, tx8);
    store_global(g_pb, acc, base, nrows, ty, tx8);
}

__global__ void __launch_bounds__(256, 1)
edge_kernel(const float* __restrict__ pos, const int* __restrict__ ei,
            const float* __restrict__ few1, const float* __restrict__ feb1,
            const float* __restrict__ few2, const float* __restrict__ feb2,
            const float* __restrict__ finfw, const float* __restrict__ finfb) {
    extern __shared__ float sm[];
    float* sA = sm;
    float* sB = sm + TILE * PADW;
    float* sW = sB + TILE * PADW;
    float* sDist = sW + HD * HD;
    float* sE    = sDist + TILE;
    int*   sSrc  = (int*)(sE + TILE);
    int*   sEnd  = sSrc + TILE;

    const int tid  = threadIdx.x;
    const int base = blockIdx.x * TILE;
    int nrows = NE - base; if (nrows > TILE) nrows = TILE;

    if (tid < TILE) {
        int s = 0, e = 0; float dist = 0.f;
        if (tid < nrows) {
            s = ei[base + tid];
            e = ei[NE + base + tid];
            float dx = pos[3 * s + 0] - pos[3 * e + 0];
            float dy = pos[3 * s + 1] - pos[3 * e + 1];
            float dz = pos[3 * s + 2] - pos[3 * e + 2];
            dx *= dx; dy *= dy; dz *= dz;               // elementwise square
            dist = sqrtf(dx * dx + dy * dy + dz * dz);  // ||d^2||_2
        }
        sSrc[tid] = s; sEnd[tid] = e; sDist[tid] = dist;
    }
    __syncthreads();

    // H1 = tanh(PA[src] + PB[end] + dist*w_row + b1)  -> sA   (fused gather)
    const float* wrow = few1 + 256 * HD;
    for (int idx = tid; idx < TILE * 32; idx += 256) {
        int r = idx >> 5, c = (idx & 31) << 2;
        float4 a = *(const float4*)(g_pa + (size_t)sSrc[r] * HD + c);
        float4 b = *(const float4*)(g_pb + (size_t)sEnd[r] * HD + c);
        float4 w = *(const float4*)(wrow + c);
        float4 bb = *(const float4*)(feb1 + c);
        float d = sDist[r];
        float4 v;
        v.x = tanhf(a.x + b.x + fmaf(d, w.x, bb.x));
        v.y = tanhf(a.y + b.y + fmaf(d, w.y, bb.y));
        v.z = tanhf(a.z + b.z + fmaf(d, w.z, bb.z));
        v.w = tanhf(a.w + b.w + fmaf(d, w.w, bb.w));
        *(float4*)(sA + r * PADW + c) = v;
    }
    load_w128(sW, few2, tid);
    __syncthreads();

    const int ty = tid >> 4, tx8 = (tid & 15) << 3;
    u64 acc[8][4];
    init_bias(acc, feb2, tx8);
    gemm128(sA, sW, acc, ty, tx8);
    store_acc<0>(sB, acc, ty, tx8);           // H2 = m_ij -> sB
    __syncthreads();

    // e_ij = tanh(H2 . finf_w + b): warp per 16 edges
    {
        int warp = tid >> 5, lane = tid & 31;
        float fw0 = finfw[lane], fw1 = finfw[lane + 32];
        float fw2 = finfw[lane + 64], fw3 = finfw[lane + 96];
        float fb = finfb[0];
        for (int it = 0; it < 16; ++it) {
            int r = warp * 16 + it;
            const float* row = sB + r * PADW;
            float v = row[lane] * fw0 + row[lane + 32] * fw1
                    + row[lane + 64] * fw2 + row[lane + 96] * fw3;
#pragma unroll
            for (int off = 16; off; off >>= 1) v += __shfl_xor_sync(0xffffffffu, v, off);
            if (lane == 0) sE[r] = tanhf(v + fb);
        }
    }
    __syncthreads();

    // scatter-add e*m to source node — vectorized red.global.add.v4.f32
    for (int idx = tid; idx < nrows * 32; idx += 256) {
        int r = idx >> 5, c = (idx & 31) << 2;
        float e = sE[r];
        float4 m = *(const float4*)(sB + r * PADW + c);
        float* p = &g_mi[(size_t)sSrc[r] * HD + c];
        asm volatile("red.global.add.v4.f32 [%0], {%1, %2, %3, %4};"
                     :: "l"(p), "f"(e * m.x), "f"(e * m.y),
                        "f"(e * m.z), "f"(e * m.w)
                     : "memory");
    }
}

__global__ void __launch_bounds__(256, 1)
node_kernel(const float* __restrict__ x,
            const float* __restrict__ fhw1, const float* __restrict__ fhb1,
            const float* __restrict__ fhw2, const float* __restrict__ fhb2,
            const float* __restrict__ l1w, const float* __restrict__ l1b,
            const float* __restrict__ l2w, const float* __restrict__ l2b,
            const float* __restrict__ l3w, const float* __restrict__ l3b,
            const float* __restrict__ l4w, const float* __restrict__ l4b,
            const float* __restrict__ l5w, const float* __restrict__ l5b,
            float* __restrict__ out) {
    extern __shared__ float sm[];
    float* sA = sm;
    float* sB = sm + TILE * PADW;
    float* sW = sB + TILE * PADW;

    const int tid  = threadIdx.x;
    const int base = blockIdx.x * TILE;
    int nrows = NN - base; if (nrows > TILE) nrows = TILE;

    for (int idx = tid; idx < TILE * 32; idx += 256) {
        int r = idx >> 5, c = (idx & 31) << 2;
        int g = base + ((r < nrows) ? r : 0);
        *(float4*)(sA + r * PADW + c) = *(const float4*)(x + (size_t)g * HD + c);
        *(float4*)(sB + r * PADW + c) = *(const float4*)(g_mi + (size_t)g * HD + c);
    }
    load_w128(sW, fhw1, tid);
    __syncthreads();

    const int ty = tid >> 4, tx8 = (tid & 15) << 3;
    u64 acc[8][4];
    init_bias(acc, fhb1, tx8);
    gemm128(sA, sW, acc, ty, tx8);
    __syncthreads();
    load_w128(sW, fhw1 + 128 * HD, tid);
    __syncthreads();
    gemm128(sB, sW, acc, ty, tx8);
    __syncthreads();
    store_acc<0>(sB, acc, ty, tx8);           // H = tanh(...) -> sB
    __syncthreads();
    load_w128(sW, fhw2, tid);
    __syncthreads();
    init_bias(acc, fhb2, tx8);
#pragma unroll
    for (int i = 0; i < 8; ++i) {             // residual: + x
        const ulonglong2* p0 = (const ulonglong2*)(sA + (ty + (i << 4)) * PADW + tx8);
        ulonglong2 x0 = p0[0], x1 = p0[1];
        add2(acc[i][0], x0.x); add2(acc[i][1], x0.y);
        add2(acc[i][2], x1.x); add2(acc[i][3], x1.y);
    }
    gemm128(sB, sW, acc, ty, tx8);
    store_acc<2>(sA, acc, ty, tx8);           // x1 -> sA
    __syncthreads();

    const float* ws[4] = {l1w, l2w, l3w, l4w};
    const float* bs[4] = {l1b, l2b, l3b, l4b};
#pragma unroll
    for (int L = 0; L < 4; ++L) {
        const float* src = (L & 1) ? sB : sA;
        float*       dst = (L & 1) ? sA : sB;
        load_w128(sW, ws[L], tid);
        __syncthreads();
        init_bias(acc, bs[L], tx8);
        gemm128(src, sW, acc, ty, tx8);
        store_acc<1>(dst, acc, ty, tx8);
        __syncthreads();
    }
    // final activations in sA

    {
        int warp = tid >> 5, lane = tid & 31;
        float w[4][3];
#pragma unroll
        for (int i = 0; i < 4; ++i) {
            int k = lane + 32 * i;
            w[i][0] = l5w[k * 3 + 0]; w[i][1] = l5w[k * 3 + 1]; w[i][2] = l5w[k * 3 + 2];
        }
        float b0 = l5b[0], b1 = l5b[1], b2 = l5b[2];
        for (int it = 0; it < 16; ++it) {
            int r = warp * 16 + it;
            const float* row = sA + r * PADW;
            float c0 = 0.f, c1 = 0.f, c2 = 0.f;
#pragma unroll
            for (int i = 0; i < 4; ++i) {
                float h = row[lane + 32 * i];
                c0 = fmaf(h, w[i][0], c0);
                c1 = fmaf(h, w[i][1], c1);
                c2 = fmaf(h, w[i][2], c2);
            }
#pragma unroll
            for (int off = 16; off; off >>= 1) {
                c0 += __shfl_xor_sync(0xffffffffu, c0, off);
                c1 += __shfl_xor_sync(0xffffffffu, c1, off);
                c2 += __shfl_xor_sync(0xffffffffu, c2, off);
            }
            if (lane == 0 && r < nrows) {
                float* o = out + (size_t)(base + r) * 3;
                o[0] = c0 + b0; o[1] = c1 + b1; o[2] = c2 + b2;
            }
        }
    }
}

// ---------------------------------------------------------------- launch

extern "C" void kernel_launch(void* const* d_in, const int* in_sizes, int n_in,
                              void* d_out, int out_size) {
    const float* x     = (const float*)d_in[0];
    const float* pos   = (const float*)d_in[1];
    const int*   ei    = (const int*)d_in[2];
    const float* few1  = (const float*)d_in[3];
    const float* feb1  = (const float*)d_in[4];
    const float* few2  = (const float*)d_in[5];
    const float* feb2  = (const float*)d_in[6];
    const float* finfw = (const float*)d_in[7];
    const float* finfb = (const float*)d_in[8];
    const float* fhw1  = (const float*)d_in[9];
    const float* fhb1  = (const float*)d_in[10];
    const float* fhw2  = (const float*)d_in[11];
    const float* fhb2  = (const float*)d_in[12];
    const float* l1w   = (const float*)d_in[13];
    const float* l1b   = (const float*)d_in[14];
    const float* l2w   = (const float*)d_in[15];
    const float* l2b   = (const float*)d_in[16];
    const float* l3w   = (const float*)d_in[17];
    const float* l3b   = (const float*)d_in[18];
    const float* l4w   = (const float*)d_in[19];
    const float* l4b   = (const float*)d_in[20];
    const float* l5w   = (const float*)d_in[21];
    const float* l5b   = (const float*)d_in[22];
    float* out = (float*)d_out;

    cudaFuncSetAttribute(pre_kernel,  cudaFuncAttributeMaxDynamicSharedMemorySize, SMEM_BYTES);
    cudaFuncSetAttribute(edge_kernel, cudaFuncAttributeMaxDynamicSharedMemorySize, SMEM_BYTES);
    cudaFuncSetAttribute(node_kernel, cudaFuncAttributeMaxDynamicSharedMemorySize, SMEM_BYTES);

    zero_mi_kernel<<<(NN * HD / 4) / 256, 256>>>();
    pre_kernel<<<(NN + TILE - 1) / TILE, 256, SMEM_BYTES>>>(x, few1);
    edge_kernel<<<(NE + TILE - 1) / TILE, 256, SMEM_BYTES>>>(
        pos, ei, few1, feb1, few2, feb2, finfw, finfb);
    node_kernel<<<(NN + TILE - 1) / TILE, 256, SMEM_BYTES>>>(
        x, fhw1, fhb1, fhw2, fhb2,
        l1w, l1b, l2w, l2b, l3w, l3b, l4w, l4b, l5w, l5b, out);
}

// round 13
// speedup vs baseline: 1.5196x; 1.1079x over previous
#include <cuda_runtime.h>
#include <math.h>

#define NN 100000
#define NE 600000
#define HD 128
#define PADW 132
#define TILE 96

typedef unsigned long long u64;

__device__ float g_mi[(size_t)NN * HD];
__device__ float g_pa[(size_t)NN * HD];   // x @ fe_w1[0:128]
__device__ float g_pb[(size_t)NN * HD];   // x @ fe_w1[128:256]

constexpr int ACT_FLOATS   = TILE * PADW;             // one activation buffer
constexpr int SMEM_NODE    = (2 * ACT_FLOATS) * 4;          // ~101 KB
constexpr int SMEM_EDGE    = (2 * ACT_FLOATS + 4 * TILE) * 4;
constexpr int SMEM_PRE     = ACT_FLOATS * 4;

// ---------------------------------------------------------------- f32x2 ops

__device__ __forceinline__ u64 dup2(float v) {
    u64 r;
    asm("mov.b64 %0, {%1, %1};" : "=l"(r) : "f"(v));
    return r;
}
__device__ __forceinline__ void unpack2(u64 p, float& lo, float& hi) {
    asm("mov.b64 {%0, %1}, %2;" : "=f"(lo), "=f"(hi) : "l"(p));
}
__device__ __forceinline__ void fma2(u64& d, u64 a, u64 b) {
    asm("fma.rn.f32x2 %0, %1, %2, %0;" : "+l"(d) : "l"(a), "l"(b));
}
__device__ __forceinline__ void add2(u64& d, u64 a) {
    asm("add.rn.f32x2 %0, %0, %1;" : "+l"(d) : "l"(a));
}

// ---------------------------------------------------------------- helpers

__device__ __forceinline__ void init_zero(u64 acc[6][4]) {
#pragma unroll
    for (int i = 0; i < 6; ++i)
#pragma unroll
        for (int j = 0; j < 4; ++j) acc[i][j] = 0ull;
}

__device__ __forceinline__ void init_bias(u64 acc[6][4],
                                          const float* __restrict__ b, int tx8) {
    ulonglong2 b0 = *(const ulonglong2*)(b + tx8);
    ulonglong2 b1 = *(const ulonglong2*)(b + tx8 + 4);
#pragma unroll
    for (int i = 0; i < 6; ++i) {
        acc[i][0] = b0.x; acc[i][1] = b0.y;
        acc[i][2] = b1.x; acc[i][3] = b1.y;
    }
}

// C[96x128] += A[96xPADW](smem) * W[128x128](gmem via L1/L2)
__device__ __forceinline__ void gemm96(const float* __restrict__ sA,
                                       const float* __restrict__ W,
                                       u64 acc[6][4], int ty, int tx8) {
    const float* a0 = sA + ty * PADW;
    const float* wp = W + tx8;
#pragma unroll 2
    for (int kk = 0; kk < HD / 4; ++kk) {
        float4 av[6];
#pragma unroll
        for (int i = 0; i < 6; ++i)
            av[i] = *(const float4*)(a0 + (i << 4) * PADW + (kk << 2));
#pragma unroll
        for (int t = 0; t < 4; ++t) {
            const int k = (kk << 2) + t;
            float4 w0 = __ldg((const float4*)(wp + k * HD));
            float4 w1 = __ldg((const float4*)(wp + k * HD + 4));
            u64 b0x, b0y, b1x, b1y;
            asm("mov.b64 %0, {%1, %2};" : "=l"(b0x) : "f"(w0.x), "f"(w0.y));
            asm("mov.b64 %0, {%1, %2};" : "=l"(b0y) : "f"(w0.z), "f"(w0.w));
            asm("mov.b64 %0, {%1, %2};" : "=l"(b1x) : "f"(w1.x), "f"(w1.y));
            asm("mov.b64 %0, {%1, %2};" : "=l"(b1y) : "f"(w1.z), "f"(w1.w));
#pragma unroll
            for (int i = 0; i < 6; ++i) {
                float as = (t == 0) ? av[i].x : (t == 1) ? av[i].y
                         : (t == 2) ? av[i].z : av[i].w;
                u64 a = dup2(as);
                fma2(acc[i][0], a, b0x);
                fma2(acc[i][1], a, b0y);
                fma2(acc[i][2], a, b1x);
                fma2(acc[i][3], a, b1y);
            }
        }
    }
}

// MODE: 0 = tanh, 1 = leaky-relu(0.01), 2 = identity
template <int MODE>
__device__ __forceinline__ void store_acc(float* __restrict__ buf,
                                          u64 acc[6][4], int ty, int tx8) {
#pragma unroll
    for (int i = 0; i < 6; ++i) {
        float v[8];
#pragma unroll
        for (int j = 0; j < 4; ++j) unpack2(acc[i][j], v[2 * j], v[2 * j + 1]);
#pragma unroll
        for (int j = 0; j < 8; ++j) {
            float t = v[j];
            if (MODE == 0)      t = tanhf(t);
            else if (MODE == 1) t = (t > 0.f) ? t : 0.01f * t;
            v[j] = t;
        }
        float* p = buf + (ty + (i << 4)) * PADW + tx8;
        *(float4*)p       = make_float4(v[0], v[1], v[2], v[3]);
        *(float4*)(p + 4) = make_float4(v[4], v[5], v[6], v[7]);
    }
}

__device__ __forceinline__ void store_global(float* __restrict__ g, u64 acc[6][4],
                                             int base, int nrows, int ty, int tx8) {
#pragma unroll
    for (int i = 0; i < 6; ++i) {
        int row = ty + (i << 4);
        if (row < nrows) {
            float v[8];
#pragma unroll
            for (int j = 0; j < 4; ++j) unpack2(acc[i][j], v[2 * j], v[2 * j + 1]);
            float* p = g + (size_t)(base + row) * HD + tx8;
            *(float4*)p       = make_float4(v[0], v[1], v[2], v[3]);
            *(float4*)(p + 4) = make_float4(v[4], v[5], v[6], v[7]);
        }
    }
}

// ---------------------------------------------------------------- kernels

__global__ void zero_mi_kernel() {
    int i = blockIdx.x * blockDim.x + threadIdx.x;
    ((float4*)g_mi)[i] = make_float4(0.f, 0.f, 0.f, 0.f);
}

__global__ void __launch_bounds__(256, 2)
pre_kernel(const float* __restrict__ x, const float* __restrict__ few1) {
    extern __shared__ float sm[];
    float* sA = sm;

    const int tid  = threadIdx.x;
    const int base = blockIdx.x * TILE;
    int nrows = NN - base; if (nrows > TILE) nrows = TILE;

    for (int idx = tid; idx < TILE * 32; idx += 256) {
        int r = idx >> 5, c = (idx & 31) << 2;
        int g = base + ((r < nrows) ? r : 0);
        *(float4*)(sA + r * PADW + c) = *(const float4*)(x + (size_t)g * HD + c);
    }
    __syncthreads();

    const int ty = tid >> 4, tx8 = (tid & 15) << 3;
    u64 acc[6][4];
    init_zero(acc);
    gemm96(sA, few1, acc, ty, tx8);                    // W_top
    store_global(g_pa, acc, base, nrows, ty, tx8);
    init_zero(acc);
    gemm96(sA, few1 + 128 * HD, acc, ty, tx8);         // W_bot
    store_global(g_pb, acc, base, nrows, ty, tx8);
}

__global__ void __launch_bounds__(256, 2)
edge_kernel(const float* __restrict__ pos, const int* __restrict__ ei,
            const float* __restrict__ few1, const float* __restrict__ feb1,
            const float* __restrict__ few2, const float* __restrict__ feb2,
            const float* __restrict__ finfw, const float* __restrict__ finfb) {
    extern __shared__ float sm[];
    float* sA = sm;
    float* sB = sm + ACT_FLOATS;
    float* sDist = sB + ACT_FLOATS;
    float* sE    = sDist + TILE;
    int*   sSrc  = (int*)(sE + TILE);
    int*   sEnd  = sSrc + TILE;

    const int tid  = threadIdx.x;
    const int base = blockIdx.x * TILE;
    int nrows = NE - base; if (nrows > TILE) nrows = TILE;

    if (tid < TILE) {
        int s = 0, e = 0; float dist = 0.f;
        if (tid < nrows) {
            s = ei[base + tid];
            e = ei[NE + base + tid];
            float dx = pos[3 * s + 0] - pos[3 * e + 0];
            float dy = pos[3 * s + 1] - pos[3 * e + 1];
            float dz = pos[3 * s + 2] - pos[3 * e + 2];
            dx *= dx; dy *= dy; dz *= dz;               // elementwise square
            dist = sqrtf(dx * dx + dy * dy + dz * dz);  // ||d^2||_2
        }
        sSrc[tid] = s; sEnd[tid] = e; sDist[tid] = dist;
    }
    __syncthreads();

    // H1 = tanh(PA[src] + PB[end] + dist*w_row + b1)  -> sA  (fused gather)
    const float* wrow = few1 + 256 * HD;
    for (int idx = tid; idx < TILE * 32; idx += 256) {
        int r = idx >> 5, c = (idx & 31) << 2;
        float4 a = *(const float4*)(g_pa + (size_t)sSrc[r] * HD + c);
        float4 b = *(const float4*)(g_pb + (size_t)sEnd[r] * HD + c);
        float4 w = *(const float4*)(wrow + c);
        float4 bb = *(const float4*)(feb1 + c);
        float d = sDist[r];
        float4 v;
        v.x = tanhf(a.x + b.x + fmaf(d, w.x, bb.x));
        v.y = tanhf(a.y + b.y + fmaf(d, w.y, bb.y));
        v.z = tanhf(a.z + b.z + fmaf(d, w.z, bb.z));
        v.w = tanhf(a.w + b.w + fmaf(d, w.w, bb.w));
        *(float4*)(sA + r * PADW + c) = v;
    }
    __syncthreads();

    const int ty = tid >> 4, tx8 = (tid & 15) << 3;
    u64 acc[6][4];
    init_bias(acc, feb2, tx8);
    gemm96(sA, few2, acc, ty, tx8);
    store_acc<0>(sB, acc, ty, tx8);           // H2 = m_ij -> sB
    __syncthreads();

    // e_ij = tanh(H2 . finf_w + b): warp per 12 edges
    {
        int warp = tid >> 5, lane = tid & 31;
        float fw0 = finfw[lane], fw1 = finfw[lane + 32];
        float fw2 = finfw[lane + 64], fw3 = finfw[lane + 96];
        float fb = finfb[0];
        for (int it = 0; it < 12; ++it) {
            int r = warp * 12 + it;
            const float* row = sB + r * PADW;
            float v = row[lane] * fw0 + row[lane + 32] * fw1
                    + row[lane + 64] * fw2 + row[lane + 96] * fw3;
#pragma unroll
            for (int off = 16; off; off >>= 1) v += __shfl_xor_sync(0xffffffffu, v, off);
            if (lane == 0) sE[r] = tanhf(v + fb);
        }
    }
    __syncthreads();

    // scatter-add e*m to source node — vectorized red.global.add.v4.f32
    for (int idx = tid; idx < nrows * 32; idx += 256) {
        int r = idx >> 5, c = (idx & 31) << 2;
        float e = sE[r];
        float4 m = *(const float4*)(sB + r * PADW + c);
        float* p = &g_mi[(size_t)sSrc[r] * HD + c];
        asm volatile("red.global.add.v4.f32 [%0], {%1, %2, %3, %4};"
                     :: "l"(p), "f"(e * m.x), "f"(e * m.y),
                        "f"(e * m.z), "f"(e * m.w)
                     : "memory");
    }
}

__global__ void __launch_bounds__(256, 2)
node_kernel(const float* __restrict__ x,
            const float* __restrict__ fhw1, const float* __restrict__ fhb1,
            const float* __restrict__ fhw2, const float* __restrict__ fhb2,
            const float* __restrict__ l1w, const float* __restrict__ l1b,
            const float* __restrict__ l2w, const float* __restrict__ l2b,
            const float* __restrict__ l3w, const float* __restrict__ l3b,
            const float* __restrict__ l4w, const float* __restrict__ l4b,
            const float* __restrict__ l5w, const float* __restrict__ l5b,
            float* __restrict__ out) {
    extern __shared__ float sm[];
    float* sA = sm;
    float* sB = sm + ACT_FLOATS;

    const int tid  = threadIdx.x;
    const int base = blockIdx.x * TILE;
    int nrows = NN - base; if (nrows > TILE) nrows = TILE;

    for (int idx = tid; idx < TILE * 32; idx += 256) {
        int r = idx >> 5, c = (idx & 31) << 2;
        int g = base + ((r < nrows) ? r : 0);
        *(float4*)(sA + r * PADW + c) = *(const float4*)(x + (size_t)g * HD + c);
        *(float4*)(sB + r * PADW + c) = *(const float4*)(g_mi + (size_t)g * HD + c);
    }
    __syncthreads();

    const int ty = tid >> 4, tx8 = (tid & 15) << 3;
    u64 acc[6][4];
    init_bias(acc, fhb1, tx8);
    gemm96(sA, fhw1, acc, ty, tx8);
    gemm96(sB, fhw1 + 128 * HD, acc, ty, tx8);
    __syncthreads();                           // sB reads done before overwrite
    store_acc<0>(sB, acc, ty, tx8);            // H = tanh(...) -> sB
    __syncthreads();
    init_bias(acc, fhb2, tx8);
#pragma unroll
    for (int i = 0; i < 6; ++i) {              // residual: + x
        const ulonglong2* p0 = (const ulonglong2*)(sA + (ty + (i << 4)) * PADW + tx8);
        ulonglong2 x0 = p0[0], x1 = p0[1];
        add2(acc[i][0], x0.x); add2(acc[i][1], x0.y);
        add2(acc[i][2], x1.x); add2(acc[i][3], x1.y);
    }
    gemm96(sB, fhw2, acc, ty, tx8);
    __syncthreads();                           // sA residual reads done
    store_acc<2>(sA, acc, ty, tx8);            // x1 -> sA
    __syncthreads();

    const float* ws[4] = {l1w, l2w, l3w, l4w};
    const float* bs[4] = {l1b, l2b, l3b, l4b};
#pragma unroll
    for (int L = 0; L < 4; ++L) {
        const float* src = (L & 1) ? sB : sA;
        float*       dst = (L & 1) ? sA : sB;
        init_bias(acc, bs[L], tx8);
        gemm96(src, ws[L], acc, ty, tx8);
        __syncthreads();
        store_acc<1>(dst, acc, ty, tx8);
        __syncthreads();
    }
    // final activations in sA (l4 wrote dst=sA)

    // l5: [128]->[3], warp per 12 rows
    {
        int warp = tid >> 5, lane = tid & 31;
        float w[4][3];
#pragma unroll
        for (int i = 0; i < 4; ++i) {
            int k = lane + 32 * i;
            w[i][0] = l5w[k * 3 + 0]; w[i][1] = l5w[k * 3 + 1]; w[i][2] = l5w[k * 3 + 2];
        }
        float b0 = l5b[0], b1 = l5b[1], b2 = l5b[2];
        for (int it = 0; it < 12; ++it) {
            int r = warp * 12 + it;
            const float* row = sA + r * PADW;
            float c0 = 0.f, c1 = 0.f, c2 = 0.f;
#pragma unroll
            for (int i = 0; i < 4; ++i) {
                float h = row[lane + 32 * i];
                c0 = fmaf(h, w[i][0], c0);
                c1 = fmaf(h, w[i][1], c1);
                c2 = fmaf(h, w[i][2], c2);
            }
#pragma unroll
            for (int off = 16; off; off >>= 1) {
                c0 += __shfl_xor_sync(0xffffffffu, c0, off);
                c1 += __shfl_xor_sync(0xffffffffu, c1, off);
                c2 += __shfl_xor_sync(0xffffffffu, c2, off);
            }
            if (lane == 0 && r < nrows) {
                float* o = out + (size_t)(base + r) * 3;
                o[0] = c0 + b0; o[1] = c1 + b1; o[2] = c2 + b2;
            }
        }
    }
}

// ---------------------------------------------------------------- launch

extern "C" void kernel_launch(void* const* d_in, const int* in_sizes, int n_in,
                              void* d_out, int out_size) {
    const float* x     = (const float*)d_in[0];
    const float* pos   = (const float*)d_in[1];
    const int*   ei    = (const int*)d_in[2];
    const float* few1  = (const float*)d_in[3];
    const float* feb1  = (const float*)d_in[4];
    const float* few2  = (const float*)d_in[5];
    const float* feb2  = (const float*)d_in[6];
    const float* finfw = (const float*)d_in[7];
    const float* finfb = (const float*)d_in[8];
    const float* fhw1  = (const float*)d_in[9];
    const float* fhb1  = (const float*)d_in[10];
    const float* fhw2  = (const float*)d_in[11];
    const float* fhb2  = (const float*)d_in[12];
    const float* l1w   = (const float*)d_in[13];
    const float* l1b   = (const float*)d_in[14];
    const float* l2w   = (const float*)d_in[15];
    const float* l2b   = (const float*)d_in[16];
    const float* l3w   = (const float*)d_in[17];
    const float* l3b   = (const float*)d_in[18];
    const float* l4w   = (const float*)d_in[19];
    const float* l4b   = (const float*)d_in[20];
    const float* l5w   = (const float*)d_in[21];
    const float* l5b   = (const float*)d_in[22];
    float* out = (float*)d_out;

    cudaFuncSetAttribute(pre_kernel,  cudaFuncAttributeMaxDynamicSharedMemorySize, SMEM_PRE);
    cudaFuncSetAttribute(edge_kernel, cudaFuncAttributeMaxDynamicSharedMemorySize, SMEM_EDGE);
    cudaFuncSetAttribute(node_kernel, cudaFuncAttributeMaxDynamicSharedMemorySize, SMEM_NODE);

    zero_mi_kernel<<<(NN * HD / 4) / 256, 256>>>();
    pre_kernel<<<(NN + TILE - 1) / TILE, 256, SMEM_PRE>>>(x, few1);
    edge_kernel<<<(NE + TILE - 1) / TILE, 256, SMEM_EDGE>>>(
        pos, ei, few1, feb1, few2, feb2, finfw, finfb);
    node_kernel<<<(NN + TILE - 1) / TILE, 256, SMEM_NODE>>>(
        x, fhw1, fhb1, fhw2, fhb2,
        l1w, l1b, l2w, l2b, l3w, l3b, l4w, l4b, l5w, l5b, out);
}